// round 1
// baseline (speedup 1.0000x reference)
#include <cuda_runtime.h>
#include <cstdint>

#define BB   32
#define HWD  1024
#define NL   32
#define CC   768
#define NH   8
#define DK   96

// Scratch (no cudaMalloc allowed): q (3MB), k/v (96MB each), att (3MB)
__device__ float g_q[(size_t)BB * CC * NL];
__device__ float g_k[(size_t)BB * HWD * CC];
__device__ float g_v[(size_t)BB * HWD * CC];
__device__ float g_att[(size_t)BB * NL * CC];

// ---------------- f32x2 helpers (sm_100+ packed fp32) ----------------
__device__ __forceinline__ unsigned long long pack2(float v) {
    unsigned long long r;
    unsigned int u = __float_as_uint(v);
    asm("mov.b64 %0, {%1, %1};" : "=l"(r) : "r"(u));
    return r;
}
__device__ __forceinline__ void fma2(unsigned long long& d, unsigned long long a,
                                     unsigned long long b) {
    asm("fma.rn.f32x2 %0, %1, %2, %0;" : "+l"(d) : "l"(a), "l"(b));
}
__device__ __forceinline__ float2 unpack2(unsigned long long v) {
    unsigned int lo, hi;
    asm("mov.b64 {%0, %1}, %2;" : "=r"(lo), "=r"(hi) : "l"(v));
    return make_float2(__uint_as_float(lo), __uint_as_float(hi));
}

__device__ __forceinline__ float warp_sum(float v) {
#pragma unroll
    for (int o = 16; o; o >>= 1) v += __shfl_xor_sync(0xffffffffu, v, o);
    return v;
}

// ---------------- Kernel 1: q = instance_norm(wq @ l) * mask ----------------
// (bq is constant over the normalized axis n_l, so it cancels exactly — skipped)
// grid (96, 32), block 256: warp w -> channel k0+w, lane -> language token n
__global__ void __launch_bounds__(256) qnorm_kernel(const float* __restrict__ lm,
                                                    const float* __restrict__ wq,
                                                    const float* __restrict__ mask) {
    int b = blockIdx.y;
    int k = blockIdx.x * 8 + (threadIdx.x >> 5);
    int lane = threadIdx.x & 31;
    __shared__ float ls[64 * NL];

    float acc = 0.f;
    for (int c0 = 0; c0 < CC; c0 += 64) {
        __syncthreads();
        const float* src = lm + ((size_t)b * CC + c0) * NL;
        for (int i = threadIdx.x; i < 64 * NL; i += 256) ls[i] = src[i];
        __syncthreads();
        const float* wp = wq + (size_t)k * CC + c0;
#pragma unroll 16
        for (int cc = 0; cc < 64; cc++) acc = fmaf(wp[cc], ls[cc * NL + lane], acc);
    }
    float mu  = warp_sum(acc) * (1.f / NL);
    float d   = acc - mu;
    float var = warp_sum(d * d) * (1.f / NL);
    float q   = d * rsqrtf(var + 1e-5f) * mask[b * NL + lane];
    g_q[((size_t)b * CC + k) * NL + lane] = q;
}

// ---------------- Kernel 2: k = x@wk^T + bk, v = x@wv^T + bv (fused GEMM) ----------------
// M=32768, N=768, K=768. BM=128, BN=64, BK=16. 256 threads, micro-tile 8x4 per
// output matrix with M-paired fma.rn.f32x2 accumulators (32 FMA2/thread/kstep).
__global__ void __launch_bounds__(256, 2) kv_kernel(const float* __restrict__ x,
                                                    const float* __restrict__ wk,
                                                    const float* __restrict__ wv,
                                                    const float* __restrict__ bk,
                                                    const float* __restrict__ bv) {
    __shared__ float xs[16][128];
    __shared__ float wks[16][64];
    __shared__ float wvs[16][64];

    int tid = threadIdx.x;
    int bm = blockIdx.x * 128;
    int bn = blockIdx.y * 64;
    int ty = tid >> 4, tx = tid & 15;

    unsigned long long ck[4][4], cv[4][4];
#pragma unroll
    for (int i = 0; i < 4; i++)
#pragma unroll
        for (int j = 0; j < 4; j++) { ck[i][j] = 0ull; cv[i][j] = 0ull; }

    for (int k0 = 0; k0 < CC; k0 += 16) {
#pragma unroll
        for (int i = 0; i < 2; i++) {
            int idx = tid + i * 256;          // 0..511
            int rr = idx >> 2;                // 0..127
            int c4 = (idx & 3) << 2;          // 0,4,8,12
            float4 t = *(const float4*)(x + (size_t)(bm + rr) * CC + k0 + c4);
            xs[c4 + 0][rr] = t.x; xs[c4 + 1][rr] = t.y;
            xs[c4 + 2][rr] = t.z; xs[c4 + 3][rr] = t.w;
        }
        {
            int rr = tid >> 2;                // 0..63
            int c4 = (tid & 3) << 2;
            float4 t = *(const float4*)(wk + (size_t)(bn + rr) * CC + k0 + c4);
            wks[c4 + 0][rr] = t.x; wks[c4 + 1][rr] = t.y;
            wks[c4 + 2][rr] = t.z; wks[c4 + 3][rr] = t.w;
            float4 u = *(const float4*)(wv + (size_t)(bn + rr) * CC + k0 + c4);
            wvs[c4 + 0][rr] = u.x; wvs[c4 + 1][rr] = u.y;
            wvs[c4 + 2][rr] = u.z; wvs[c4 + 3][rr] = u.w;
        }
        __syncthreads();
#pragma unroll
        for (int kk = 0; kk < 16; kk++) {
            ulonglong2 A0 = *(const ulonglong2*)&xs[kk][ty * 8];
            ulonglong2 A1 = *(const ulonglong2*)&xs[kk][ty * 8 + 4];
            unsigned long long a2[4] = {A0.x, A0.y, A1.x, A1.y};
            float4 bkf = *(const float4*)&wks[kk][tx * 4];
            float4 bvf = *(const float4*)&wvs[kk][tx * 4];
            unsigned long long bk2[4], bv2[4];
            bk2[0] = pack2(bkf.x); bk2[1] = pack2(bkf.y);
            bk2[2] = pack2(bkf.z); bk2[3] = pack2(bkf.w);
            bv2[0] = pack2(bvf.x); bv2[1] = pack2(bvf.y);
            bv2[2] = pack2(bvf.z); bv2[3] = pack2(bvf.w);
#pragma unroll
            for (int i2 = 0; i2 < 4; i2++) {
#pragma unroll
                for (int j = 0; j < 4; j++) {
                    fma2(ck[i2][j], a2[i2], bk2[j]);
                    fma2(cv[i2][j], a2[i2], bv2[j]);
                }
            }
        }
        __syncthreads();
    }

    float bkb[4], bvb[4];
#pragma unroll
    for (int j = 0; j < 4; j++) {
        bkb[j] = bk[bn + tx * 4 + j];
        bvb[j] = bv[bn + tx * 4 + j];
    }
#pragma unroll
    for (int i2 = 0; i2 < 4; i2++) {
        size_t base = (size_t)(bm + ty * 8 + i2 * 2) * CC + bn + tx * 4;
        float2 u0 = unpack2(ck[i2][0]), u1 = unpack2(ck[i2][1]);
        float2 u2 = unpack2(ck[i2][2]), u3 = unpack2(ck[i2][3]);
        *(float4*)(g_k + base) =
            make_float4(u0.x + bkb[0], u1.x + bkb[1], u2.x + bkb[2], u3.x + bkb[3]);
        *(float4*)(g_k + base + CC) =
            make_float4(u0.y + bkb[0], u1.y + bkb[1], u2.y + bkb[2], u3.y + bkb[3]);
        u0 = unpack2(cv[i2][0]); u1 = unpack2(cv[i2][1]);
        u2 = unpack2(cv[i2][2]); u3 = unpack2(cv[i2][3]);
        *(float4*)(g_v + base) =
            make_float4(u0.x + bvb[0], u1.x + bvb[1], u2.x + bvb[2], u3.x + bvb[3]);
        *(float4*)(g_v + base + CC) =
            make_float4(u0.y + bvb[0], u1.y + bvb[1], u2.y + bvb[2], u3.y + bvb[3]);
    }
}

// ---------------- Kernel 3: attention per (b, h) ----------------
// sim[n,l] = scale * k[n,:]·q[:,l] + 10000*(m-1); softmax over l (per n);
// att[l,d] = sum_n P[n,l] * v[n,d]. Block = 256 threads, 8-row n-chunks.
__global__ void __launch_bounds__(256) attn_kernel(const float* __restrict__ mask) {
    int h = blockIdx.x, b = blockIdx.y;
    __shared__ float q_s[DK * NL];   // [d][l]
    __shared__ float k_s[8][DK];
    __shared__ float v_s[8][DK];
    __shared__ float p_s[8][NL];

    int tid = threadIdx.x, w = tid >> 5, lane = tid & 31;
    const float* qb = g_q + ((size_t)b * CC + h * DK) * NL;
    for (int i = tid; i < DK * NL; i += 256) q_s[i] = qb[i];

    float mterm = 10000.f * (mask[b * NL + lane] - 1.f);
    const float scale = 0.03608439182435161f;   // 768^-0.5

    float acc[12];
#pragma unroll
    for (int j = 0; j < 12; j++) acc[j] = 0.f;
    int lt = tid >> 3, r = tid & 7;

    const float* kbase = g_k + (size_t)b * HWD * CC + h * DK;
    const float* vbase = g_v + (size_t)b * HWD * CC + h * DK;

    for (int n0 = 0; n0 < HWD; n0 += 8) {
        __syncthreads();
        if (tid < 192) {                         // 8 rows x 24 float4
            int rr = tid / 24, c4 = (tid % 24) * 4;
            *(float4*)&k_s[rr][c4] = *(const float4*)(kbase + (size_t)(n0 + rr) * CC + c4);
            *(float4*)&v_s[rr][c4] = *(const float4*)(vbase + (size_t)(n0 + rr) * CC + c4);
        }
        __syncthreads();

        float s = 0.f;
#pragma unroll
        for (int d4 = 0; d4 < DK; d4 += 4) {
            float4 kv4 = *(const float4*)&k_s[w][d4];
            s = fmaf(kv4.x, q_s[(d4 + 0) * NL + lane], s);
            s = fmaf(kv4.y, q_s[(d4 + 1) * NL + lane], s);
            s = fmaf(kv4.z, q_s[(d4 + 2) * NL + lane], s);
            s = fmaf(kv4.w, q_s[(d4 + 3) * NL + lane], s);
        }
        s = fmaf(s, scale, mterm);

        float mx = s;
#pragma unroll
        for (int o = 16; o; o >>= 1) mx = fmaxf(mx, __shfl_xor_sync(0xffffffffu, mx, o));
        float e = __expf(s - mx);
        float sm = e;
#pragma unroll
        for (int o = 16; o; o >>= 1) sm += __shfl_xor_sync(0xffffffffu, sm, o);
        p_s[w][lane] = e / sm;
        __syncthreads();

#pragma unroll
        for (int nn = 0; nn < 8; nn++) {
            float p = p_s[nn][lt];
#pragma unroll
            for (int j = 0; j < 12; j++) acc[j] = fmaf(p, v_s[nn][r + 8 * j], acc[j]);
        }
    }

    float* op = g_att + ((size_t)b * NL + lt) * CC + h * DK + r;
#pragma unroll
    for (int j = 0; j < 12; j++) op[8 * j] = acc[j];
}

// ---------------- Kernel 4: out = instance_norm(wo @ att) (bo cancels) ----------------
// grid (96, 32): warp -> output channel co, lane -> language token l.
__global__ void __launch_bounds__(256) out_kernel(const float* __restrict__ wo,
                                                  float* __restrict__ out) {
    int b = blockIdx.y;
    int co = blockIdx.x * 8 + (threadIdx.x >> 5);
    int lane = threadIdx.x & 31;
    __shared__ float as[NL][65];   // padded: bank (l+vv)%32, conflict-free

    float acc = 0.f;
    for (int v0 = 0; v0 < CC; v0 += 64) {
        __syncthreads();
        const float* src = g_att + (size_t)b * NL * CC + v0;
        for (int i = threadIdx.x; i < NL * 64; i += 256) {
            int row = i >> 6, cc = i & 63;
            as[row][cc] = src[(size_t)row * CC + cc];
        }
        __syncthreads();
        const float* wp = wo + (size_t)co * CC + v0;
#pragma unroll 16
        for (int vv = 0; vv < 64; vv++) acc = fmaf(wp[vv], as[lane][vv], acc);
    }
    float mu  = warp_sum(acc) * (1.f / NL);
    float d   = acc - mu;
    float var = warp_sum(d * d) * (1.f / NL);
    float val = d * rsqrtf(var + 1e-5f);
    out[((size_t)b * NL + lane) * CC + co] = val;   // final shape (B, n_l, Co)
}

// ---------------- launch ----------------
extern "C" void kernel_launch(void* const* d_in, const int* in_sizes, int n_in,
                              void* d_out, int out_size) {
    const float* x    = (const float*)d_in[0];
    const float* l    = (const float*)d_in[1];
    const float* mask = (const float*)d_in[2];
    const float* wq   = (const float*)d_in[3];
    // d_in[4] = bq: cancels under instance_norm (constant over n_l) — unused
    const float* wk   = (const float*)d_in[5];
    const float* bk   = (const float*)d_in[6];
    const float* wv   = (const float*)d_in[7];
    const float* bv   = (const float*)d_in[8];
    const float* wo   = (const float*)d_in[9];
    // d_in[10] = bo: cancels under instance_norm — unused
    float* out = (float*)d_out;

    qnorm_kernel<<<dim3(96, 32), 256>>>(l, wq, mask);
    kv_kernel<<<dim3(256, 12), 256>>>(x, wk, wv, bk, bv);
    attn_kernel<<<dim3(8, 32), 256>>>(mask);
    out_kernel<<<dim3(96, 32), 256>>>(wo, out);
}

// round 2
// speedup vs baseline: 2.1846x; 2.1846x over previous
#include <cuda_runtime.h>
#include <cstdint>

#define BB   32
#define HWD  1024
#define NL   32
#define CC   768
#define NH   8
#define DK   96

// Scratch (no cudaMalloc allowed)
__device__ float g_q [(size_t)BB * CC * NL];          // [b][c=h*96+d][l]   3MB
__device__ float g_fk[(size_t)BB * CC * 256];         // [b][c][hl]        25MB
__device__ float g_tb[(size_t)BB * 256];              // [b][hl]
__device__ float g_P [(size_t)BB * HWD * 256];        // [b][n][hl]        33MB
__device__ float g_G [(size_t)BB * 256 * CC];         // [b][hl][c]        25MB
__device__ float g_ps[(size_t)BB * 256];              // [b][hl] = sum_n P
__device__ float g_att[(size_t)BB * NL * CC];         // [b][l][v]          3MB

// ---------------- f32x2 helpers ----------------
__device__ __forceinline__ unsigned long long pack2(float v) {
    unsigned long long r; unsigned int u = __float_as_uint(v);
    asm("mov.b64 %0, {%1, %1};" : "=l"(r) : "r"(u));
    return r;
}
__device__ __forceinline__ void fma2(unsigned long long& d, unsigned long long a,
                                     unsigned long long b) {
    asm("fma.rn.f32x2 %0, %1, %2, %0;" : "+l"(d) : "l"(a), "l"(b));
}
__device__ __forceinline__ float2 unpack2(unsigned long long v) {
    unsigned int lo, hi;
    asm("mov.b64 {%0, %1}, %2;" : "=r"(lo), "=r"(hi) : "l"(v));
    return make_float2(__uint_as_float(lo), __uint_as_float(hi));
}
__device__ __forceinline__ float warp_sum(float v) {
#pragma unroll
    for (int o = 16; o; o >>= 1) v += __shfl_xor_sync(0xffffffffu, v, o);
    return v;
}

// ---------------- K1: q = instance_norm(wq @ l) * mask  (bq cancels) ----------------
__global__ void __launch_bounds__(256) qnorm_kernel(const float* __restrict__ lm,
                                                    const float* __restrict__ wq,
                                                    const float* __restrict__ mask) {
    int b = blockIdx.y;
    int k = blockIdx.x * 8 + (threadIdx.x >> 5);
    int lane = threadIdx.x & 31;
    __shared__ float ls[64 * NL];

    float acc = 0.f;
    for (int c0 = 0; c0 < CC; c0 += 64) {
        __syncthreads();
        const float* src = lm + ((size_t)b * CC + c0) * NL;
        for (int i = threadIdx.x; i < 64 * NL; i += 256) ls[i] = src[i];
        __syncthreads();
        const float* wp = wq + (size_t)k * CC + c0;
#pragma unroll 16
        for (int cc = 0; cc < 64; cc++) acc = fmaf(wp[cc], ls[cc * NL + lane], acc);
    }
    float mu  = warp_sum(acc) * (1.f / NL);
    float d   = acc - mu;
    float var = warp_sum(d * d) * (1.f / NL);
    float q   = d * rsqrtf(var + 1e-5f) * mask[b * NL + lane];
    g_q[((size_t)b * CC + k) * NL + lane] = q;
}

// ---------------- K2: fk[b][c][hl] = sum_d wk[h*96+d][c] * q[b][h*96+d][l]
//                      tb[b][hl]    = sum_d bk[h*96+d]    * q[b][h*96+d][l]
// warp handles (b, h, 4 consecutive c); lane = l.
__global__ void __launch_bounds__(256) fold_kernel(const float* __restrict__ wk,
                                                   const float* __restrict__ bk) {
    int wid = blockIdx.x * 8 + (threadIdx.x >> 5);   // 0 .. 49151
    int lane = threadIdx.x & 31;
    int cg = wid % 192;           // c-group of 4
    int h  = (wid / 192) & 7;
    int b  = wid / 1536;
    int c  = cg * 4;

    const float* qb = g_q + ((size_t)b * CC + h * DK) * NL;
    float a0 = 0.f, a1 = 0.f, a2 = 0.f, a3 = 0.f, at = 0.f;
#pragma unroll 4
    for (int d = 0; d < DK; d++) {
        float qv = qb[d * NL + lane];
        float4 w4 = *(const float4*)(wk + (size_t)(h * DK + d) * CC + c);
        a0 = fmaf(w4.x, qv, a0);
        a1 = fmaf(w4.y, qv, a1);
        a2 = fmaf(w4.z, qv, a2);
        a3 = fmaf(w4.w, qv, a3);
        if (cg == 0) at = fmaf(bk[h * DK + d], qv, at);
    }
    size_t base = ((size_t)b * CC + c) * 256 + h * NL + lane;
    g_fk[base]         = a0;
    g_fk[base + 256]   = a1;
    g_fk[base + 512]   = a2;
    g_fk[base + 768]   = a3;
    if (cg == 0) g_tb[b * 256 + h * NL + lane] = at;
}

// ---------------- K3: S = x @ fk, +tb, *scale, +mask, softmax over each head's 32 l, -> P
// BM=128 (n), BN=64 (2 heads), BK=16. grid (8 mtile, 4 headpair, 32 b), 256 thr.
__global__ void __launch_bounds__(256) sim_kernel(const float* __restrict__ x,
                                                  const float* __restrict__ mask) {
    __shared__ float xs[16][128];
    __shared__ float fs[16][64];
    __shared__ float Ssm[128][68];
    __shared__ float tbs[64];
    __shared__ float ms[32];

    int tid = threadIdx.x;
    int bm = blockIdx.x * 128;
    int hp = blockIdx.y;           // head pair
    int b  = blockIdx.z;
    int ty = tid >> 4, tx = tid & 15;

    if (tid < 64) tbs[tid] = g_tb[b * 256 + hp * 64 + tid];
    if (tid < 32) ms[tid]  = mask[b * NL + tid];

    unsigned long long ck[4][4];
#pragma unroll
    for (int i = 0; i < 4; i++)
#pragma unroll
        for (int j = 0; j < 4; j++) ck[i][j] = 0ull;

    for (int k0 = 0; k0 < CC; k0 += 16) {
#pragma unroll
        for (int i = 0; i < 2; i++) {
            int idx = tid + i * 256;
            int rr = idx >> 2;               // m (n row) 0..127
            int c4 = (idx & 3) << 2;         // k 0..15
            float4 t = *(const float4*)(x + ((size_t)b * HWD + bm + rr) * CC + k0 + c4);
            xs[c4 + 0][rr] = t.x; xs[c4 + 1][rr] = t.y;
            xs[c4 + 2][rr] = t.z; xs[c4 + 3][rr] = t.w;
        }
        {
            int rr = tid >> 4;               // k 0..15
            int c4 = (tid & 15) << 2;        // hl 0..63
            float4 t = *(const float4*)(g_fk + ((size_t)b * CC + k0 + rr) * 256 + hp * 64 + c4);
            *(float4*)&fs[rr][c4] = t;
        }
        __syncthreads();
#pragma unroll
        for (int kk = 0; kk < 16; kk++) {
            ulonglong2 A0 = *(const ulonglong2*)&xs[kk][ty * 8];
            ulonglong2 A1 = *(const ulonglong2*)&xs[kk][ty * 8 + 4];
            unsigned long long a2v[4] = {A0.x, A0.y, A1.x, A1.y};
            float4 bf = *(const float4*)&fs[kk][tx * 4];
            unsigned long long b2[4];
            b2[0] = pack2(bf.x); b2[1] = pack2(bf.y);
            b2[2] = pack2(bf.z); b2[3] = pack2(bf.w);
#pragma unroll
            for (int i2 = 0; i2 < 4; i2++)
#pragma unroll
                for (int j = 0; j < 4; j++) fma2(ck[i2][j], a2v[i2], b2[j]);
        }
        __syncthreads();
    }

    // stash raw S in smem
#pragma unroll
    for (int i2 = 0; i2 < 4; i2++) {
        int r0 = ty * 8 + i2 * 2;
#pragma unroll
        for (int j = 0; j < 4; j++) {
            float2 u = unpack2(ck[i2][j]);
            Ssm[r0][tx * 4 + j]     = u.x;
            Ssm[r0 + 1][tx * 4 + j] = u.y;
        }
    }
    __syncthreads();

    // softmax: thread -> (row, head)
    {
        int row = tid >> 1, head = tid & 1;
        const float scale = 0.03608439182435161f;   // 768^-0.5
        float* rp = &Ssm[row][head * 32];
        float mx = -1e30f;
        float sv[32];
#pragma unroll
        for (int i = 0; i < 32; i++) {
            float s = fmaf(rp[i] + tbs[head * 32 + i], scale, 10000.f * (ms[i] - 1.f));
            sv[i] = s;
            mx = fmaxf(mx, s);
        }
        float sum = 0.f;
#pragma unroll
        for (int i = 0; i < 32; i++) {
            float e = __expf(sv[i] - mx);
            sv[i] = e;
            sum += e;
        }
        float inv = __frcp_rn(sum);
#pragma unroll
        for (int i = 0; i < 32; i++) rp[i] = sv[i] * inv;
    }
    __syncthreads();

    // write P[b][n][hl] (each thread: one row-half, 8 float4)
    {
        int row = tid >> 1, half = tid & 1;
        float* dst = g_P + ((size_t)b * HWD + bm + row) * 256 + hp * 64 + half * 32;
#pragma unroll
        for (int j = 0; j < 8; j++)
            *(float4*)(dst + j * 4) = *(const float4*)&Ssm[row][half * 32 + j * 4];
    }
}

// ---------------- K4: G[b][hl][c] = sum_n P[b][n][hl] * x[b][n][c]  (+psum on ny==0)
// per-batch GEMM M=256(hl) N=768(c) K=1024(n). BM=128, BN=64, BK=16. grid (2,12,32).
__global__ void __launch_bounds__(256, 2) g_kernel(const float* __restrict__ x) {
    __shared__ float Ps[16][128];
    __shared__ float Bs[16][64];

    int tid = threadIdx.x;
    int m0 = blockIdx.x * 128;
    int bn = blockIdx.y * 64;
    int b  = blockIdx.z;
    int ty = tid >> 4, tx = tid & 15;
    bool psOn = (blockIdx.y == 0);

    unsigned long long cg[4][4], psacc[4];
#pragma unroll
    for (int i = 0; i < 4; i++) {
        psacc[i] = 0ull;
#pragma unroll
        for (int j = 0; j < 4; j++) cg[i][j] = 0ull;
    }
    const unsigned long long one2 = pack2(1.0f);

    for (int k0 = 0; k0 < HWD; k0 += 16) {
#pragma unroll
        for (int i = 0; i < 2; i++) {
            int idx = tid + i * 256;
            int rr = idx >> 5;               // k 0..15
            int c4 = (idx & 31) << 2;        // m 0..127
            float4 t = *(const float4*)(g_P + ((size_t)b * HWD + k0 + rr) * 256 + m0 + c4);
            *(float4*)&Ps[rr][c4] = t;
        }
        {
            int rr = tid >> 4;               // k 0..15
            int c4 = (tid & 15) << 2;        // c 0..63
            float4 t = *(const float4*)(x + ((size_t)b * HWD + k0 + rr) * CC + bn + c4);
            *(float4*)&Bs[rr][c4] = t;
        }
        __syncthreads();
#pragma unroll
        for (int kk = 0; kk < 16; kk++) {
            ulonglong2 A0 = *(const ulonglong2*)&Ps[kk][ty * 8];
            ulonglong2 A1 = *(const ulonglong2*)&Ps[kk][ty * 8 + 4];
            unsigned long long a2v[4] = {A0.x, A0.y, A1.x, A1.y};
            float4 bf = *(const float4*)&Bs[kk][tx * 4];
            unsigned long long b2[4];
            b2[0] = pack2(bf.x); b2[1] = pack2(bf.y);
            b2[2] = pack2(bf.z); b2[3] = pack2(bf.w);
#pragma unroll
            for (int i2 = 0; i2 < 4; i2++)
#pragma unroll
                for (int j = 0; j < 4; j++) fma2(cg[i2][j], a2v[i2], b2[j]);
            if (psOn) {
#pragma unroll
                for (int i2 = 0; i2 < 4; i2++) fma2(psacc[i2], a2v[i2], one2);
            }
        }
        __syncthreads();
    }

#pragma unroll
    for (int i2 = 0; i2 < 4; i2++) {
        size_t base = ((size_t)b * 256 + m0 + ty * 8 + i2 * 2) * CC + bn + tx * 4;
        float2 u0 = unpack2(cg[i2][0]), u1 = unpack2(cg[i2][1]);
        float2 u2 = unpack2(cg[i2][2]), u3 = unpack2(cg[i2][3]);
        *(float4*)(g_G + base)      = make_float4(u0.x, u1.x, u2.x, u3.x);
        *(float4*)(g_G + base + CC) = make_float4(u0.y, u1.y, u2.y, u3.y);
    }
    if (psOn && tx == 0) {
#pragma unroll
        for (int i2 = 0; i2 < 4; i2++) {
            float2 u = unpack2(psacc[i2]);
            int m = m0 + ty * 8 + i2 * 2;
            g_ps[b * 256 + m]     = u.x;
            g_ps[b * 256 + m + 1] = u.y;
        }
    }
}

// ---------------- K5: att[b][l][h*96+dv] = sum_c wv[h*96+dv][c] G[b][h*32+l][c] + bv*psum
// grid (8 h, 32 b), 256 thr; micro 3dv x 4l.
__global__ void __launch_bounds__(256) att_kernel(const float* __restrict__ wv,
                                                  const float* __restrict__ bv) {
    __shared__ float gs[32][65];
    __shared__ float ws[96][65];

    int tid = threadIdx.x;
    int h = blockIdx.x, b = blockIdx.y;
    int lg = tid >> 5;        // 0..7 -> l = lg*4..+3
    int dvg = tid & 31;       // dv = dvg*3..+2

    float acc[3][4];
#pragma unroll
    for (int i = 0; i < 3; i++)
#pragma unroll
        for (int j = 0; j < 4; j++) acc[i][j] = 0.f;

    for (int c0 = 0; c0 < CC; c0 += 64) {
        __syncthreads();
#pragma unroll
        for (int i = 0; i < 2; i++) {
            int idx = tid + i * 256;
            int rr = idx >> 4, c4 = (idx & 15) << 2;
            float4 t = *(const float4*)(g_G + ((size_t)b * 256 + h * 32 + rr) * CC + c0 + c4);
            gs[rr][c4] = t.x; gs[rr][c4 + 1] = t.y; gs[rr][c4 + 2] = t.z; gs[rr][c4 + 3] = t.w;
        }
#pragma unroll
        for (int i = 0; i < 6; i++) {
            int idx = tid + i * 256;
            int rr = idx >> 4, c4 = (idx & 15) << 2;
            float4 t = *(const float4*)(wv + ((size_t)(h * DK) + rr) * CC + c0 + c4);
            ws[rr][c4] = t.x; ws[rr][c4 + 1] = t.y; ws[rr][c4 + 2] = t.z; ws[rr][c4 + 3] = t.w;
        }
        __syncthreads();
#pragma unroll 8
        for (int cc = 0; cc < 64; cc++) {
            float w0 = ws[dvg * 3][cc], w1 = ws[dvg * 3 + 1][cc], w2 = ws[dvg * 3 + 2][cc];
            float g0 = gs[lg * 4][cc], g1 = gs[lg * 4 + 1][cc];
            float g2 = gs[lg * 4 + 2][cc], g3 = gs[lg * 4 + 3][cc];
            acc[0][0] = fmaf(w0, g0, acc[0][0]); acc[0][1] = fmaf(w0, g1, acc[0][1]);
            acc[0][2] = fmaf(w0, g2, acc[0][2]); acc[0][3] = fmaf(w0, g3, acc[0][3]);
            acc[1][0] = fmaf(w1, g0, acc[1][0]); acc[1][1] = fmaf(w1, g1, acc[1][1]);
            acc[1][2] = fmaf(w1, g2, acc[1][2]); acc[1][3] = fmaf(w1, g3, acc[1][3]);
            acc[2][0] = fmaf(w2, g0, acc[2][0]); acc[2][1] = fmaf(w2, g1, acc[2][1]);
            acc[2][2] = fmaf(w2, g2, acc[2][2]); acc[2][3] = fmaf(w2, g3, acc[2][3]);
        }
    }
#pragma unroll
    for (int i = 0; i < 3; i++) {
        int dv = dvg * 3 + i;
        float bvv = bv[h * DK + dv];
#pragma unroll
        for (int j = 0; j < 4; j++) {
            int l = lg * 4 + j;
            float ps = g_ps[b * 256 + h * 32 + l];
            g_att[((size_t)b * NL + l) * CC + h * DK + dv] = acc[i][j] + bvv * ps;
        }
    }
}

// ---------------- K6: out = instance_norm(wo @ att) over l, write [b][l][o] (bo cancels)
// grid (8 co-tiles of 96, 32 b), 256 thr; micro 3co x 4l.
__global__ void __launch_bounds__(256) out_kernel(const float* __restrict__ wo,
                                                  float* __restrict__ out) {
    __shared__ float as_[32][65];
    __shared__ float ws[96][65];
    __shared__ float S[96][33];

    int tid = threadIdx.x;
    int co0 = blockIdx.x * 96;
    int b = blockIdx.y;
    int lg = tid >> 5;
    int cg = tid & 31;

    float acc[3][4];
#pragma unroll
    for (int i = 0; i < 3; i++)
#pragma unroll
        for (int j = 0; j < 4; j++) acc[i][j] = 0.f;

    for (int c0 = 0; c0 < CC; c0 += 64) {
        __syncthreads();
#pragma unroll
        for (int i = 0; i < 2; i++) {
            int idx = tid + i * 256;
            int rr = idx >> 4, c4 = (idx & 15) << 2;
            float4 t = *(const float4*)(g_att + ((size_t)b * NL + rr) * CC + c0 + c4);
            as_[rr][c4] = t.x; as_[rr][c4 + 1] = t.y; as_[rr][c4 + 2] = t.z; as_[rr][c4 + 3] = t.w;
        }
#pragma unroll
        for (int i = 0; i < 6; i++) {
            int idx = tid + i * 256;
            int rr = idx >> 4, c4 = (idx & 15) << 2;
            float4 t = *(const float4*)(wo + ((size_t)(co0 + rr)) * CC + c0 + c4);
            ws[rr][c4] = t.x; ws[rr][c4 + 1] = t.y; ws[rr][c4 + 2] = t.z; ws[rr][c4 + 3] = t.w;
        }
        __syncthreads();
#pragma unroll 8
        for (int cc = 0; cc < 64; cc++) {
            float w0 = ws[cg * 3][cc], w1 = ws[cg * 3 + 1][cc], w2 = ws[cg * 3 + 2][cc];
            float a0 = as_[lg * 4][cc], a1 = as_[lg * 4 + 1][cc];
            float a2 = as_[lg * 4 + 2][cc], a3 = as_[lg * 4 + 3][cc];
            acc[0][0] = fmaf(w0, a0, acc[0][0]); acc[0][1] = fmaf(w0, a1, acc[0][1]);
            acc[0][2] = fmaf(w0, a2, acc[0][2]); acc[0][3] = fmaf(w0, a3, acc[0][3]);
            acc[1][0] = fmaf(w1, a0, acc[1][0]); acc[1][1] = fmaf(w1, a1, acc[1][1]);
            acc[1][2] = fmaf(w1, a2, acc[1][2]); acc[1][3] = fmaf(w1, a3, acc[1][3]);
            acc[2][0] = fmaf(w2, a0, acc[2][0]); acc[2][1] = fmaf(w2, a1, acc[2][1]);
            acc[2][2] = fmaf(w2, a2, acc[2][2]); acc[2][3] = fmaf(w2, a3, acc[2][3]);
        }
    }
#pragma unroll
    for (int i = 0; i < 3; i++)
#pragma unroll
        for (int j = 0; j < 4; j++) S[cg * 3 + i][lg * 4 + j] = acc[i][j];
    __syncthreads();

    if (tid < 96) {
        float v[32];
        float mu = 0.f;
#pragma unroll
        for (int l = 0; l < 32; l++) { v[l] = S[tid][l]; mu += v[l]; }
        mu *= (1.f / 32.f);
        float var = 0.f;
#pragma unroll
        for (int l = 0; l < 32; l++) { float d = v[l] - mu; var = fmaf(d, d, var); }
        float r = rsqrtf(var * (1.f / 32.f) + 1e-5f);
#pragma unroll
        for (int l = 0; l < 32; l++)
            out[((size_t)b * NL + l) * CC + co0 + tid] = (v[l] - mu) * r;
    }
}

// ---------------- launch ----------------
extern "C" void kernel_launch(void* const* d_in, const int* in_sizes, int n_in,
                              void* d_out, int out_size) {
    const float* x    = (const float*)d_in[0];
    const float* l    = (const float*)d_in[1];
    const float* mask = (const float*)d_in[2];
    const float* wq   = (const float*)d_in[3];
    // d_in[4] = bq: cancels under instance_norm — unused
    const float* wk   = (const float*)d_in[5];
    const float* bk   = (const float*)d_in[6];
    const float* wv   = (const float*)d_in[7];
    const float* bv   = (const float*)d_in[8];
    const float* wo   = (const float*)d_in[9];
    // d_in[10] = bo: cancels under instance_norm — unused
    float* out = (float*)d_out;

    qnorm_kernel<<<dim3(96, 32), 256>>>(l, wq, mask);
    fold_kernel<<<6144, 256>>>(wk, bk);
    sim_kernel<<<dim3(8, 4, 32), 256>>>(x, mask);
    g_kernel<<<dim3(2, 12, 32), 256>>>(x);
    att_kernel<<<dim3(8, 32), 256>>>(wv, bv);
    out_kernel<<<dim3(8, 32), 256>>>(wo, out);
}